// round 3
// baseline (speedup 1.0000x reference)
#include <cuda_runtime.h>

typedef unsigned long long ull_t;

#define TILE_M 64
#define LDA 260
#define LDB 260
#define LDX 36

// shared-memory layout (float offsets)
#define SM_MIX  0
#define SM_WORK (TILE_M * LDA)                // 16640
#define SM_BS0  (2 * TILE_M * LDA)            // 33280
#define SM_BS1  (SM_BS0 + 32 * LDB)
#define SM_XS   (SM_BS1 + 32 * LDB)
#define SM_C    (SM_XS + TILE_M * LDX)
#define SM_WSM  (SM_C + 256)
#define SM_FLOATS (SM_WSM + 32)

__device__ __forceinline__ ull_t pack2(float x) {
    ull_t r; asm("mov.b64 %0, {%1, %1};" : "=l"(r) : "f"(x)); return r;
}
__device__ __forceinline__ void ffma2(ull_t& d, ull_t a, ull_t b) {
    asm("fma.rn.f32x2 %0, %1, %2, %0;" : "+l"(d) : "l"(a), "l"(b));
}
__device__ __forceinline__ float2 unpack2(ull_t v) {
    float lo, hi; asm("mov.b64 {%0, %1}, %2;" : "=f"(lo), "=f"(hi) : "l"(v));
    return make_float2(lo, hi);
}
__device__ __forceinline__ float4 ldg4(const float* p) {
    return __ldg(reinterpret_cast<const float4*>(p));
}
__device__ __forceinline__ float elu1(float v) { return v > 0.f ? v : (expf(v) - 1.f); }
__device__ __forceinline__ float sigm(float v) { return 1.f / (1.f + expf(-v)); }

// 32-k-step microtile: 8 rows x 8 cols per thread, f32x2 accumulators.
// acc[r][0..1] -> cols (c0..c0+3), acc[r][2..3] -> cols (c0+128..c0+131)
__device__ __forceinline__ void mma_tile(const float* __restrict__ As, int lda,
                                         const float* __restrict__ Bs,
                                         int rowBase, int c0, ull_t acc[8][4])
{
#pragma unroll 2
    for (int kq = 0; kq < 8; ++kq) {
        float4 av[8];
#pragma unroll
        for (int r = 0; r < 8; ++r)
            av[r] = *reinterpret_cast<const float4*>(As + (rowBase + r) * lda + kq * 4);
#pragma unroll
        for (int kk = 0; kk < 4; ++kk) {
            const float* brow = Bs + (kq * 4 + kk) * LDB;
            ulonglong2 b0 = *reinterpret_cast<const ulonglong2*>(brow + c0);
            ulonglong2 b1 = *reinterpret_cast<const ulonglong2*>(brow + c0 + 128);
#pragma unroll
            for (int r = 0; r < 8; ++r) {
                float a = (kk == 0) ? av[r].x : (kk == 1) ? av[r].y
                        : (kk == 2) ? av[r].z : av[r].w;
                ull_t ap = pack2(a);
                ffma2(acc[r][0], ap, b0.x);
                ffma2(acc[r][1], ap, b0.y);
                ffma2(acc[r][2], ap, b1.x);
                ffma2(acc[r][3], ap, b1.y);
            }
        }
    }
}

// Weight staging: GMEM W[n][k] (k contiguous) -> smem Bs[k][n] tile (KT=32)
__device__ __forceinline__ void stage_load(const float* __restrict__ Wg, int kt,
                                           int tid, float4 w[8])
{
    int k0g = tid & 7, nb = tid >> 3;
#pragma unroll
    for (int p = 0; p < 8; ++p)
        w[p] = ldg4(Wg + (nb + p * 32) * 256 + kt + k0g * 4);
}
__device__ __forceinline__ void stage_store(float* Bs, int tid, const float4 w[8])
{
    int k0 = (tid & 7) * 4, nb = tid >> 3;
#pragma unroll
    for (int p = 0; p < 8; ++p) {
        int n = nb + p * 32;
        Bs[(k0 + 0) * LDB + n] = w[p].x;
        Bs[(k0 + 1) * LDB + n] = w[p].y;
        Bs[(k0 + 2) * LDB + n] = w[p].z;
        Bs[(k0 + 3) * LDB + n] = w[p].w;
    }
}

// K=256 GEMM, double-buffered staging with LDG prefetch under compute.
__device__ __forceinline__ void gemm256(const float* __restrict__ As, int lda,
                                        const float* __restrict__ Wg,
                                        float* bs0, float* bs1,
                                        int tid, int rowBase, int c0, ull_t acc[8][4])
{
    float4 w[8];
    stage_load(Wg, 0, tid, w);
    stage_store(bs0, tid, w);
    __syncthreads();
#pragma unroll 1
    for (int t = 0; t < 8; ++t) {
        if (t < 7) stage_load(Wg, (t + 1) * 32, tid, w);
        mma_tile(As + t * 32, lda, (t & 1) ? bs1 : bs0, rowBase, c0, acc);
        if (t < 7) stage_store((t & 1) ? bs0 : bs1, tid, w);
        __syncthreads();
    }
}

__global__ void __launch_bounds__(256, 1)
vsn_kernel(const float* __restrict__ x,
           const float* __restrict__ proj_w,
           const float* __restrict__ proj_b,
           const float* __restrict__ sc_lnb,
           const float* __restrict__ fc1w, const float* __restrict__ fc1b,
           const float* __restrict__ fc2w, const float* __restrict__ fc2b,
           const float* __restrict__ gatew, const float* __restrict__ gateb,
           const float* __restrict__ lng,  const float* __restrict__ lnbv,
           float* __restrict__ out)
{
    extern __shared__ float sm[];
    float* mixs = sm + SM_MIX;
    float* work = sm + SM_WORK;
    float* bs0  = sm + SM_BS0;
    float* bs1  = sm + SM_BS1;
    float* xs   = sm + SM_XS;
    float* cs   = sm + SM_C;
    float* wsm  = sm + SM_WSM;

    const int tid = threadIdx.x;
    const int cg = tid & 31, rg = tid >> 5;
    const int rowBase = rg * 8;
    const int c0 = cg * 4;
    const int row0 = blockIdx.x * TILE_M;

    // ---- scorer collapse: softmax weights from sc_ln_b only ----
    if (tid < 32) {
        float v = sc_lnb[tid];
        float mx = v;
#pragma unroll
        for (int o = 16; o; o >>= 1) mx = fmaxf(mx, __shfl_xor_sync(0xffffffffu, mx, o));
        float e = expf(v - mx);
        float se = e;
#pragma unroll
        for (int o = 16; o; o >>= 1) se += __shfl_xor_sync(0xffffffffu, se, o);
        wsm[tid] = e / se;
    }
    __syncthreads();

    // stage scaled proj_w into bs0 as [f][d] (no transpose needed)
    for (int q = tid; q < 2048; q += 256) {
        int f = q >> 6, c4 = (q & 63) * 4;
        float wv = wsm[f];
        float4 v = ldg4(proj_w + f * 256 + c4);
        v.x *= wv; v.y *= wv; v.z *= wv; v.w *= wv;
        *reinterpret_cast<float4*>(bs0 + f * LDB + c4) = v;
    }
    // bias mixture c[d] = sum_f W[f] * proj_b[f][d]
    {
        float a = 0.f;
#pragma unroll
        for (int f = 0; f < 32; ++f)
            a += wsm[f] * __ldg(proj_b + f * 256 + tid);
        cs[tid] = a;
    }
    // stage x rows [64][32] into xs
    for (int q = tid; q < 512; q += 256) {
        int m = q >> 3, fq = (q & 7) * 4;
        float4 v = *reinterpret_cast<const float4*>(x + (size_t)(row0 + m) * 32 + fq);
        *reinterpret_cast<float4*>(xs + m * LDX + fq) = v;
    }
    __syncthreads();

    ull_t acc[8][4];

    // ---- GEMM0: mix = xs @ pw + c  (K=32, single tile) ----
#pragma unroll
    for (int r = 0; r < 8; ++r)
#pragma unroll
        for (int j = 0; j < 4; ++j) acc[r][j] = 0ULL;
    mma_tile(xs, LDX, bs0, rowBase, c0, acc);
    {
        float4 ca = *reinterpret_cast<const float4*>(cs + c0);
        float4 cb = *reinterpret_cast<const float4*>(cs + c0 + 128);
#pragma unroll
        for (int r = 0; r < 8; ++r) {
            int m = rowBase + r;
            float2 p0 = unpack2(acc[r][0]), p1 = unpack2(acc[r][1]);
            float2 p2 = unpack2(acc[r][2]), p3 = unpack2(acc[r][3]);
            float4 o0 = make_float4(p0.x + ca.x, p0.y + ca.y, p1.x + ca.z, p1.y + ca.w);
            float4 o1 = make_float4(p2.x + cb.x, p2.y + cb.y, p3.x + cb.z, p3.y + cb.w);
            *reinterpret_cast<float4*>(mixs + m * LDA + c0)       = o0;
            *reinterpret_cast<float4*>(mixs + m * LDA + c0 + 128) = o1;
        }
    }
    __syncthreads();

    // ---- GEMM1: h = elu(mix @ fc1w^T + b1) -> work ----
#pragma unroll
    for (int r = 0; r < 8; ++r)
#pragma unroll
        for (int j = 0; j < 4; ++j) acc[r][j] = 0ULL;
    gemm256(mixs, LDA, fc1w, bs0, bs1, tid, rowBase, c0, acc);
    {
        float4 ba = ldg4(fc1b + c0);
        float4 bb = ldg4(fc1b + c0 + 128);
#pragma unroll
        for (int r = 0; r < 8; ++r) {
            int m = rowBase + r;
            float2 p0 = unpack2(acc[r][0]), p1 = unpack2(acc[r][1]);
            float2 p2 = unpack2(acc[r][2]), p3 = unpack2(acc[r][3]);
            float4 o0 = make_float4(elu1(p0.x + ba.x), elu1(p0.y + ba.y),
                                    elu1(p1.x + ba.z), elu1(p1.y + ba.w));
            float4 o1 = make_float4(elu1(p2.x + bb.x), elu1(p2.y + bb.y),
                                    elu1(p3.x + bb.z), elu1(p3.y + bb.w));
            *reinterpret_cast<float4*>(work + m * LDA + c0)       = o0;
            *reinterpret_cast<float4*>(work + m * LDA + c0 + 128) = o1;
        }
    }
    __syncthreads();

    // ---- GEMM2: h2b = h @ fc2w^T + b2 -> work (overwrite after reads done) ----
#pragma unroll
    for (int r = 0; r < 8; ++r)
#pragma unroll
        for (int j = 0; j < 4; ++j) acc[r][j] = 0ULL;
    gemm256(work, LDA, fc2w, bs0, bs1, tid, rowBase, c0, acc);
    {
        float4 ba = ldg4(fc2b + c0);
        float4 bb = ldg4(fc2b + c0 + 128);
#pragma unroll
        for (int r = 0; r < 8; ++r) {
            int m = rowBase + r;
            float2 p0 = unpack2(acc[r][0]), p1 = unpack2(acc[r][1]);
            float2 p2 = unpack2(acc[r][2]), p3 = unpack2(acc[r][3]);
            float4 o0 = make_float4(p0.x + ba.x, p0.y + ba.y, p1.x + ba.z, p1.y + ba.w);
            float4 o1 = make_float4(p2.x + bb.x, p2.y + bb.y, p3.x + bb.z, p3.y + bb.w);
            *reinterpret_cast<float4*>(work + m * LDA + c0)       = o0;
            *reinterpret_cast<float4*>(work + m * LDA + c0 + 128) = o1;
        }
    }
    __syncthreads();

    // ---- GEMM3: g2 = sigmoid(h2b @ gatew^T + gb); y2 = g2*h2b + (1-g2)*mix; LN ----
#pragma unroll
    for (int r = 0; r < 8; ++r)
#pragma unroll
        for (int j = 0; j < 4; ++j) acc[r][j] = 0ULL;
    gemm256(work, LDA, gatew, bs0, bs1, tid, rowBase, c0, acc);

    float4 gba = ldg4(gateb + c0);
    float4 gbb = ldg4(gateb + c0 + 128);
    float y2v[8][8];
    float sr[8], qr[8];
#pragma unroll
    for (int r = 0; r < 8; ++r) {
        int m = rowBase + r;
        float4 h0 = *reinterpret_cast<const float4*>(work + m * LDA + c0);
        float4 h1 = *reinterpret_cast<const float4*>(work + m * LDA + c0 + 128);
        float4 m0 = *reinterpret_cast<const float4*>(mixs + m * LDA + c0);
        float4 m1 = *reinterpret_cast<const float4*>(mixs + m * LDA + c0 + 128);
        float2 p0 = unpack2(acc[r][0]), p1 = unpack2(acc[r][1]);
        float2 p2 = unpack2(acc[r][2]), p3 = unpack2(acc[r][3]);
        float gv[8] = { p0.x + gba.x, p0.y + gba.y, p1.x + gba.z, p1.y + gba.w,
                        p2.x + gbb.x, p2.y + gbb.y, p3.x + gbb.z, p3.y + gbb.w };
        float hv[8] = { h0.x, h0.y, h0.z, h0.w, h1.x, h1.y, h1.z, h1.w };
        float mv[8] = { m0.x, m0.y, m0.z, m0.w, m1.x, m1.y, m1.z, m1.w };
        float s = 0.f, q = 0.f;
#pragma unroll
        for (int j = 0; j < 8; ++j) {
            float g2 = sigm(gv[j]);
            float y = g2 * hv[j] + (1.f - g2) * mv[j];
            y2v[r][j] = y;
            s += y; q += y * y;
        }
        sr[r] = s; qr[r] = q;
    }
    // warp owns its 8 rows entirely -> shuffle reduction for LN stats
#pragma unroll
    for (int r = 0; r < 8; ++r) {
#pragma unroll
        for (int o = 16; o; o >>= 1) {
            sr[r] += __shfl_xor_sync(0xffffffffu, sr[r], o);
            qr[r] += __shfl_xor_sync(0xffffffffu, qr[r], o);
        }
    }
    float4 lg0 = ldg4(lng + c0),  lg1 = ldg4(lng + c0 + 128);
    float4 lb0 = ldg4(lnbv + c0), lb1 = ldg4(lnbv + c0 + 128);
#pragma unroll
    for (int r = 0; r < 8; ++r) {
        float mean = sr[r] * (1.f / 256.f);
        float var  = qr[r] * (1.f / 256.f) - mean * mean;
        float inv  = rsqrtf(var + 1e-5f);
        float4 o0, o1;
        o0.x = (y2v[r][0] - mean) * inv * lg0.x + lb0.x;
        o0.y = (y2v[r][1] - mean) * inv * lg0.y + lb0.y;
        o0.z = (y2v[r][2] - mean) * inv * lg0.z + lb0.z;
        o0.w = (y2v[r][3] - mean) * inv * lg0.w + lb0.w;
        o1.x = (y2v[r][4] - mean) * inv * lg1.x + lb1.x;
        o1.y = (y2v[r][5] - mean) * inv * lg1.y + lb1.y;
        o1.z = (y2v[r][6] - mean) * inv * lg1.z + lb1.z;
        o1.w = (y2v[r][7] - mean) * inv * lg1.w + lb1.w;
        size_t go = (size_t)(row0 + rowBase + r) * 256;
        *reinterpret_cast<float4*>(out + go + c0)       = o0;
        *reinterpret_cast<float4*>(out + go + c0 + 128) = o1;
    }
}

extern "C" void kernel_launch(void* const* d_in, const int* in_sizes, int n_in,
                              void* d_out, int out_size)
{
    const float* x      = (const float*)d_in[0];
    const float* proj_w = (const float*)d_in[1];
    const float* proj_b = (const float*)d_in[2];
    const float* sc_lnb = (const float*)d_in[12];
    const float* fc1w   = (const float*)d_in[13];
    const float* fc1b   = (const float*)d_in[14];
    const float* fc2w   = (const float*)d_in[15];
    const float* fc2b   = (const float*)d_in[16];
    const float* gatew  = (const float*)d_in[17];
    const float* gateb  = (const float*)d_in[18];
    const float* lng    = (const float*)d_in[19];
    const float* lnbv   = (const float*)d_in[20];

    size_t smem = (size_t)SM_FLOATS * sizeof(float);  // ~210 KB
    cudaFuncSetAttribute(vsn_kernel, cudaFuncAttributeMaxDynamicSharedMemorySize, (int)smem);
    vsn_kernel<<<128, 256, smem>>>(x, proj_w, proj_b, sc_lnb,
                                   fc1w, fc1b, fc2w, fc2b,
                                   gatew, gateb, lng, lnbv,
                                   (float*)d_out);
}

// round 4
// speedup vs baseline: 1.0397x; 1.0397x over previous
#include <cuda_runtime.h>

typedef unsigned long long ull_t;

#define TILE_M 64
#define LDA 260
#define LDB 260
#define LDX 36

// shared-memory layout (float offsets)
#define SM_MIX  0
#define SM_WORK (TILE_M * LDA)                // 16640
#define SM_BS0  (2 * TILE_M * LDA)            // 33280
#define SM_BS1  (SM_BS0 + 32 * LDB)
#define SM_XS   (SM_BS1 + 32 * LDB)
#define SM_C    (SM_XS + TILE_M * LDX)
#define SM_WSM  (SM_C + 256)
#define SM_RED  (SM_WSM + 32)                 // 128 sums + 128 sumsq
#define SM_FLOATS (SM_RED + 256)

__device__ __forceinline__ ull_t pack2(float x) {
    ull_t r; asm("mov.b64 %0, {%1, %1};" : "=l"(r) : "f"(x)); return r;
}
__device__ __forceinline__ void ffma2(ull_t& d, ull_t a, ull_t b) {
    asm("fma.rn.f32x2 %0, %1, %2, %0;" : "+l"(d) : "l"(a), "l"(b));
}
__device__ __forceinline__ float2 unpack2(ull_t v) {
    float lo, hi; asm("mov.b64 {%0, %1}, %2;" : "=f"(lo), "=f"(hi) : "l"(v));
    return make_float2(lo, hi);
}
__device__ __forceinline__ float4 ldg4(const float* p) {
    return __ldg(reinterpret_cast<const float4*>(p));
}
__device__ __forceinline__ float elu1(float v) { return v > 0.f ? v : (expf(v) - 1.f); }
__device__ __forceinline__ float sigm(float v) { return 1.f / (1.f + expf(-v)); }

// 32-k-step microtile: 8 rows x 4 cols per thread (warp = 8 rows x 128 cols).
// A loads are warp-broadcast (1 smem phase); B loads 512B/warp (4 phases).
__device__ __forceinline__ void mma_tile(const float* __restrict__ As, int lda,
                                         const float* __restrict__ Bs,
                                         int rowBase, int c0, ull_t acc[8][2])
{
#pragma unroll 2
    for (int kq = 0; kq < 8; ++kq) {
        float4 av[8];
#pragma unroll
        for (int r = 0; r < 8; ++r)
            av[r] = *reinterpret_cast<const float4*>(As + (rowBase + r) * lda + kq * 4);
#pragma unroll
        for (int kk = 0; kk < 4; ++kk) {
            const float* brow = Bs + (kq * 4 + kk) * LDB;
            ulonglong2 b = *reinterpret_cast<const ulonglong2*>(brow + c0);
#pragma unroll
            for (int r = 0; r < 8; ++r) {
                float a = (kk == 0) ? av[r].x : (kk == 1) ? av[r].y
                        : (kk == 2) ? av[r].z : av[r].w;
                ull_t ap = pack2(a);
                ffma2(acc[r][0], ap, b.x);
                ffma2(acc[r][1], ap, b.y);
            }
        }
    }
}

// Weight staging (512 threads): GMEM W[n][k] (k contiguous) -> smem Bs[k][n], KT=32
__device__ __forceinline__ void stage_load(const float* __restrict__ Wg, int kt,
                                           int tid, float4 w[4])
{
    int k0g = tid & 7, n0 = tid >> 3;          // n0: 0..63
#pragma unroll
    for (int p = 0; p < 4; ++p)
        w[p] = ldg4(Wg + (n0 + p * 64) * 256 + kt + k0g * 4);
}
__device__ __forceinline__ void stage_store(float* Bs, int tid, const float4 w[4])
{
    int k0 = (tid & 7) * 4, n0 = tid >> 3;
#pragma unroll
    for (int p = 0; p < 4; ++p) {
        int n = n0 + p * 64;
        Bs[(k0 + 0) * LDB + n] = w[p].x;
        Bs[(k0 + 1) * LDB + n] = w[p].y;
        Bs[(k0 + 2) * LDB + n] = w[p].z;
        Bs[(k0 + 3) * LDB + n] = w[p].w;
    }
}

// K=256 GEMM, double-buffered staging with LDG prefetch under compute.
__device__ __forceinline__ void gemm256(const float* __restrict__ As, int lda,
                                        const float* __restrict__ Wg,
                                        float* bs0, float* bs1,
                                        int tid, int rowBase, int c0, ull_t acc[8][2])
{
    float4 w[4];
    stage_load(Wg, 0, tid, w);
    stage_store(bs0, tid, w);
    __syncthreads();
#pragma unroll 1
    for (int t = 0; t < 8; ++t) {
        if (t < 7) stage_load(Wg, (t + 1) * 32, tid, w);
        mma_tile(As + t * 32, lda, (t & 1) ? bs1 : bs0, rowBase, c0, acc);
        if (t < 7) stage_store((t & 1) ? bs0 : bs1, tid, w);
        __syncthreads();
    }
}

__global__ void __launch_bounds__(512, 1)
vsn_kernel(const float* __restrict__ x,
           const float* __restrict__ proj_w,
           const float* __restrict__ proj_b,
           const float* __restrict__ sc_lnb,
           const float* __restrict__ fc1w, const float* __restrict__ fc1b,
           const float* __restrict__ fc2w, const float* __restrict__ fc2b,
           const float* __restrict__ gatew, const float* __restrict__ gateb,
           const float* __restrict__ lng,  const float* __restrict__ lnbv,
           float* __restrict__ out)
{
    extern __shared__ float sm[];
    float* mixs = sm + SM_MIX;
    float* work = sm + SM_WORK;
    float* bs0  = sm + SM_BS0;
    float* bs1  = sm + SM_BS1;
    float* xs   = sm + SM_XS;
    float* cs   = sm + SM_C;
    float* wsm  = sm + SM_WSM;
    float* reds = sm + SM_RED;        // [64][2] row half-sums
    float* redq = sm + SM_RED + 128;  // [64][2] row half-sumsq

    const int tid = threadIdx.x;
    const int cg = tid & 31;
    const int wid = tid >> 5;
    const int rg = wid >> 1;          // row group 0..7
    const int colhalf = wid & 1;      // which 128-col half
    const int rowBase = rg * 8;
    const int c0 = cg * 4 + colhalf * 128;
    const int row0 = blockIdx.x * TILE_M;

    // ---- scorer collapse: softmax weights from sc_ln_b only ----
    if (tid < 32) {
        float v = sc_lnb[tid];
        float mx = v;
#pragma unroll
        for (int o = 16; o; o >>= 1) mx = fmaxf(mx, __shfl_xor_sync(0xffffffffu, mx, o));
        float e = expf(v - mx);
        float se = e;
#pragma unroll
        for (int o = 16; o; o >>= 1) se += __shfl_xor_sync(0xffffffffu, se, o);
        wsm[tid] = e / se;
    }
    __syncthreads();

    // stage scaled proj_w into bs0 as [f][d] (already [k][n])
    for (int q = tid; q < 2048; q += 512) {
        int f = q >> 6, c4 = (q & 63) * 4;
        float wv = wsm[f];
        float4 v = ldg4(proj_w + f * 256 + c4);
        v.x *= wv; v.y *= wv; v.z *= wv; v.w *= wv;
        *reinterpret_cast<float4*>(bs0 + f * LDB + c4) = v;
    }
    // bias mixture c[d] = sum_f W[f] * proj_b[f][d]
    if (tid < 256) {
        float a = 0.f;
#pragma unroll
        for (int f = 0; f < 32; ++f)
            a += wsm[f] * __ldg(proj_b + f * 256 + tid);
        cs[tid] = a;
    }
    // stage x rows [64][32] into xs (one float4 per thread)
    {
        int m = tid >> 3, fq = (tid & 7) * 4;
        float4 v = *reinterpret_cast<const float4*>(x + (size_t)(row0 + m) * 32 + fq);
        *reinterpret_cast<float4*>(xs + m * LDX + fq) = v;
    }
    __syncthreads();

    ull_t acc[8][2];

    // ---- GEMM0: mix = xs @ pw + c  (K=32, single tile) ----
#pragma unroll
    for (int r = 0; r < 8; ++r) { acc[r][0] = 0ULL; acc[r][1] = 0ULL; }
    mma_tile(xs, LDX, bs0, rowBase, c0, acc);
    {
        float4 ca = *reinterpret_cast<const float4*>(cs + c0);
#pragma unroll
        for (int r = 0; r < 8; ++r) {
            int m = rowBase + r;
            float2 p0 = unpack2(acc[r][0]), p1 = unpack2(acc[r][1]);
            float4 o0 = make_float4(p0.x + ca.x, p0.y + ca.y, p1.x + ca.z, p1.y + ca.w);
            *reinterpret_cast<float4*>(mixs + m * LDA + c0) = o0;
        }
    }
    __syncthreads();

    // ---- GEMM1: h = elu(mix @ fc1w^T + b1) -> work ----
#pragma unroll
    for (int r = 0; r < 8; ++r) { acc[r][0] = 0ULL; acc[r][1] = 0ULL; }
    gemm256(mixs, LDA, fc1w, bs0, bs1, tid, rowBase, c0, acc);
    {
        float4 ba = ldg4(fc1b + c0);
#pragma unroll
        for (int r = 0; r < 8; ++r) {
            int m = rowBase + r;
            float2 p0 = unpack2(acc[r][0]), p1 = unpack2(acc[r][1]);
            float4 o0 = make_float4(elu1(p0.x + ba.x), elu1(p0.y + ba.y),
                                    elu1(p1.x + ba.z), elu1(p1.y + ba.w));
            *reinterpret_cast<float4*>(work + m * LDA + c0) = o0;
        }
    }
    __syncthreads();

    // ---- GEMM2: h2b = h @ fc2w^T + b2 -> work ----
#pragma unroll
    for (int r = 0; r < 8; ++r) { acc[r][0] = 0ULL; acc[r][1] = 0ULL; }
    gemm256(work, LDA, fc2w, bs0, bs1, tid, rowBase, c0, acc);
    {
        float4 ba = ldg4(fc2b + c0);
#pragma unroll
        for (int r = 0; r < 8; ++r) {
            int m = rowBase + r;
            float2 p0 = unpack2(acc[r][0]), p1 = unpack2(acc[r][1]);
            float4 o0 = make_float4(p0.x + ba.x, p0.y + ba.y, p1.x + ba.z, p1.y + ba.w);
            *reinterpret_cast<float4*>(work + m * LDA + c0) = o0;
        }
    }
    __syncthreads();

    // ---- GEMM3: g2 = sigmoid(h2b @ gatew^T + gb); y2 = g2*h2b + (1-g2)*mix; LN ----
#pragma unroll
    for (int r = 0; r < 8; ++r) { acc[r][0] = 0ULL; acc[r][1] = 0ULL; }
    gemm256(work, LDA, gatew, bs0, bs1, tid, rowBase, c0, acc);

    float4 gba = ldg4(gateb + c0);
    float y2v[8][4];
    float sr[8], qr[8];
#pragma unroll
    for (int r = 0; r < 8; ++r) {
        int m = rowBase + r;
        float4 h0 = *reinterpret_cast<const float4*>(work + m * LDA + c0);
        float4 m0 = *reinterpret_cast<const float4*>(mixs + m * LDA + c0);
        float2 p0 = unpack2(acc[r][0]), p1 = unpack2(acc[r][1]);
        float gv[4] = { p0.x + gba.x, p0.y + gba.y, p1.x + gba.z, p1.y + gba.w };
        float hv[4] = { h0.x, h0.y, h0.z, h0.w };
        float mv[4] = { m0.x, m0.y, m0.z, m0.w };
        float s = 0.f, q = 0.f;
#pragma unroll
        for (int j = 0; j < 4; ++j) {
            float g2 = sigm(gv[j]);
            float y = g2 * hv[j] + (1.f - g2) * mv[j];
            y2v[r][j] = y;
            s += y; q += y * y;
        }
        sr[r] = s; qr[r] = q;
    }
    // warp covers 8 rows x 128 cols -> shuffle reduce, combine halves via smem
#pragma unroll
    for (int r = 0; r < 8; ++r) {
#pragma unroll
        for (int o = 16; o; o >>= 1) {
            sr[r] += __shfl_xor_sync(0xffffffffu, sr[r], o);
            qr[r] += __shfl_xor_sync(0xffffffffu, qr[r], o);
        }
    }
    if (cg == 0) {
#pragma unroll
        for (int r = 0; r < 8; ++r) {
            reds[(rowBase + r) * 2 + colhalf] = sr[r];
            redq[(rowBase + r) * 2 + colhalf] = qr[r];
        }
    }
    __syncthreads();

    float4 lg0 = ldg4(lng + c0);
    float4 lb0 = ldg4(lnbv + c0);
#pragma unroll
    for (int r = 0; r < 8; ++r) {
        int m = rowBase + r;
        float ssum = reds[m * 2] + reds[m * 2 + 1];
        float qsum = redq[m * 2] + redq[m * 2 + 1];
        float mean = ssum * (1.f / 256.f);
        float var  = qsum * (1.f / 256.f) - mean * mean;
        float inv  = rsqrtf(var + 1e-5f);
        float4 o0;
        o0.x = (y2v[r][0] - mean) * inv * lg0.x + lb0.x;
        o0.y = (y2v[r][1] - mean) * inv * lg0.y + lb0.y;
        o0.z = (y2v[r][2] - mean) * inv * lg0.z + lb0.z;
        o0.w = (y2v[r][3] - mean) * inv * lg0.w + lb0.w;
        size_t go = (size_t)(row0 + m) * 256;
        *reinterpret_cast<float4*>(out + go + c0) = o0;
    }
}

extern "C" void kernel_launch(void* const* d_in, const int* in_sizes, int n_in,
                              void* d_out, int out_size)
{
    const float* x      = (const float*)d_in[0];
    const float* proj_w = (const float*)d_in[1];
    const float* proj_b = (const float*)d_in[2];
    const float* sc_lnb = (const float*)d_in[12];
    const float* fc1w   = (const float*)d_in[13];
    const float* fc1b   = (const float*)d_in[14];
    const float* fc2w   = (const float*)d_in[15];
    const float* fc2b   = (const float*)d_in[16];
    const float* gatew  = (const float*)d_in[17];
    const float* gateb  = (const float*)d_in[18];
    const float* lng    = (const float*)d_in[19];
    const float* lnbv   = (const float*)d_in[20];

    size_t smem = (size_t)SM_FLOATS * sizeof(float);  // ~211 KB
    cudaFuncSetAttribute(vsn_kernel, cudaFuncAttributeMaxDynamicSharedMemorySize, (int)smem);
    vsn_kernel<<<128, 512, smem>>>(x, proj_w, proj_b, sc_lnb,
                                   fc1w, fc1b, fc2w, fc2b,
                                   gatew, gateb, lng, lnbv,
                                   (float*)d_out);
}